// round 1
// baseline (speedup 1.0000x reference)
#include <cuda_runtime.h>

#define CH 64
#define MAXN 65536

// Scratch (no allocs allowed): aggregation buffer + GraphNorm reductions.
__device__ __align__(16) float g_agg[(size_t)MAXN * CH];
__device__ float g_colsum[CH];
__device__ float g_varsum[CH];
__device__ int   g_idx64;

// ---------------------------------------------------------------------------
// K1: agg = x  (GIN: h = (1+0)*x + sum), zero reductions, detect index dtype.
// ---------------------------------------------------------------------------
__global__ void k_init(const float4* __restrict__ x4, const int* __restrict__ ei32,
                       int n4, int E) {
    float4* a4 = reinterpret_cast<float4*>(g_agg);
    for (int i = blockIdx.x * blockDim.x + threadIdx.x; i < n4;
         i += gridDim.x * blockDim.x)
        a4[i] = x4[i];
    if (blockIdx.x == 0) {
        if (threadIdx.x < CH) {
            g_colsum[threadIdx.x] = 0.f;
            g_varsum[threadIdx.x] = 0.f;
        }
        if (threadIdx.x == 0) {
            // int64 edge_index => high 32-bit word of every entry is 0.
            int allz = 1;
            int cnt = (E < 64) ? E : 64;
            for (int t = 0; t < cnt; t++) allz &= (ei32[2 * t + 1] == 0);
            g_idx64 = allz;
        }
    }
}

// ---------------------------------------------------------------------------
// K2: edge scatter-add. One thread per (edge, float4-chunk): 16 chunks/edge.
// Vector atomic red.global.add.v4.f32 (sm_90+) => 1 RED.128 per 16 bytes.
// ---------------------------------------------------------------------------
__global__ void k_scatter(const void* __restrict__ ei, const float4* __restrict__ x4,
                          int E) {
    const int total = E * 16;
    const int idx64 = g_idx64;
    const long long* e64 = (const long long*)ei;
    const int*       e32 = (const int*)ei;
    for (int i = blockIdx.x * blockDim.x + threadIdx.x; i < total;
         i += gridDim.x * blockDim.x) {
        int e = i >> 4;
        int c = i & 15;
        int src, dst;
        if (idx64) { src = (int)e64[e]; dst = (int)e64[E + e]; }
        else       { src = e32[e];      dst = e32[E + e]; }
        float4 v = x4[src * 16 + c];
        float* d = g_agg + dst * CH + c * 4;
        asm volatile("red.global.add.v4.f32 [%0], {%1,%2,%3,%4};"
                     :: "l"(d), "f"(v.x), "f"(v.y), "f"(v.z), "f"(v.w)
                     : "memory");
    }
}

// ---------------------------------------------------------------------------
// K3: fused MLP: (h @ W0^T -> LN -> ReLU) -> (@ W1^T -> LN -> ReLU),
// warp-per-row, 2 output channels per lane. Also accumulates column sums
// for GraphNorm mean. Writes h2 into d_out (reused as scratch).
// W stored in smem with pad-to-68 rows: float4 rows stay 16B-aligned and the
// per-phase bank pattern (l*4+k mod 32, l in 0..7) is conflict-free.
// ---------------------------------------------------------------------------
__global__ void k_mlp(const float* __restrict__ W0, const float* __restrict__ ln0w,
                      const float* __restrict__ ln0b, const float* __restrict__ W1,
                      const float* __restrict__ ln1w, const float* __restrict__ ln1b,
                      float* __restrict__ out, int N) {
    __shared__ float sW0[CH][68];
    __shared__ float sW1[CH][68];
    __shared__ float hbuf[8][CH];
    __shared__ float bsum[CH];

    const int tid  = threadIdx.x;
    const int lane = tid & 31;
    const int warp = tid >> 5;

    for (int i = tid; i < CH * CH; i += blockDim.x) {
        sW0[i >> 6][i & 63] = W0[i];
        sW1[i >> 6][i & 63] = W1[i];
    }
    if (tid < CH) bsum[tid] = 0.f;

    const float w0a = ln0w[lane], w0b = ln0w[lane + 32];
    const float b0a = ln0b[lane], b0b = ln0b[lane + 32];
    const float w1a = ln1w[lane], w1b = ln1w[lane + 32];
    const float b1a = ln1b[lane], b1b = ln1b[lane + 32];
    __syncthreads();

    const float4* wa0 = reinterpret_cast<const float4*>(&sW0[lane][0]);
    const float4* wb0 = reinterpret_cast<const float4*>(&sW0[lane + 32][0]);
    const float4* wa1 = reinterpret_cast<const float4*>(&sW1[lane][0]);
    const float4* wb1 = reinterpret_cast<const float4*>(&sW1[lane + 32][0]);
    const float4* h4  = reinterpret_cast<const float4*>(&hbuf[warp][0]);

    float cs0 = 0.f, cs1 = 0.f;

    for (int row = blockIdx.x * 8 + warp; row < N; row += gridDim.x * 8) {
        const float* hr = g_agg + (size_t)row * CH;
        hbuf[warp][lane]      = hr[lane];
        hbuf[warp][lane + 32] = hr[lane + 32];
        __syncwarp();

        // ---- layer 0 GEMM ----
        float a0e = 0.f, a0o = 0.f, a1e = 0.f, a1o = 0.f;
        #pragma unroll
        for (int kk = 0; kk < 16; kk += 2) {
            float4 hv = h4[kk];
            float4 va = wa0[kk];
            float4 vb = wb0[kk];
            a0e = fmaf(hv.x, va.x, a0e); a0e = fmaf(hv.y, va.y, a0e);
            a0e = fmaf(hv.z, va.z, a0e); a0e = fmaf(hv.w, va.w, a0e);
            a1e = fmaf(hv.x, vb.x, a1e); a1e = fmaf(hv.y, vb.y, a1e);
            a1e = fmaf(hv.z, vb.z, a1e); a1e = fmaf(hv.w, vb.w, a1e);
            float4 hv2 = h4[kk + 1];
            float4 va2 = wa0[kk + 1];
            float4 vb2 = wb0[kk + 1];
            a0o = fmaf(hv2.x, va2.x, a0o); a0o = fmaf(hv2.y, va2.y, a0o);
            a0o = fmaf(hv2.z, va2.z, a0o); a0o = fmaf(hv2.w, va2.w, a0o);
            a1o = fmaf(hv2.x, vb2.x, a1o); a1o = fmaf(hv2.y, vb2.y, a1o);
            a1o = fmaf(hv2.z, vb2.z, a1o); a1o = fmaf(hv2.w, vb2.w, a1o);
        }
        float a0 = a0e + a0o, a1 = a1e + a1o;

        // ---- LayerNorm 0 + ReLU ----
        float s = a0 + a1;
        #pragma unroll
        for (int o = 16; o; o >>= 1) s += __shfl_xor_sync(0xffffffffu, s, o);
        float mu = s * (1.f / 64.f);
        float d0 = a0 - mu, d1 = a1 - mu;
        float q = d0 * d0 + d1 * d1;
        #pragma unroll
        for (int o = 16; o; o >>= 1) q += __shfl_xor_sync(0xffffffffu, q, o);
        float inv = rsqrtf(q * (1.f / 64.f) + 1e-5f);
        float v0 = fmaxf(fmaf(d0 * inv, w0a, b0a), 0.f);
        float v1 = fmaxf(fmaf(d1 * inv, w0b, b0b), 0.f);

        __syncwarp();
        hbuf[warp][lane]      = v0;
        hbuf[warp][lane + 32] = v1;
        __syncwarp();

        // ---- layer 1 GEMM ----
        a0e = 0.f; a0o = 0.f; a1e = 0.f; a1o = 0.f;
        #pragma unroll
        for (int kk = 0; kk < 16; kk += 2) {
            float4 hv = h4[kk];
            float4 va = wa1[kk];
            float4 vb = wb1[kk];
            a0e = fmaf(hv.x, va.x, a0e); a0e = fmaf(hv.y, va.y, a0e);
            a0e = fmaf(hv.z, va.z, a0e); a0e = fmaf(hv.w, va.w, a0e);
            a1e = fmaf(hv.x, vb.x, a1e); a1e = fmaf(hv.y, vb.y, a1e);
            a1e = fmaf(hv.z, vb.z, a1e); a1e = fmaf(hv.w, vb.w, a1e);
            float4 hv2 = h4[kk + 1];
            float4 va2 = wa1[kk + 1];
            float4 vb2 = wb1[kk + 1];
            a0o = fmaf(hv2.x, va2.x, a0o); a0o = fmaf(hv2.y, va2.y, a0o);
            a0o = fmaf(hv2.z, va2.z, a0o); a0o = fmaf(hv2.w, va2.w, a0o);
            a1o = fmaf(hv2.x, vb2.x, a1o); a1o = fmaf(hv2.y, vb2.y, a1o);
            a1o = fmaf(hv2.z, vb2.z, a1o); a1o = fmaf(hv2.w, vb2.w, a1o);
        }
        a0 = a0e + a0o; a1 = a1e + a1o;

        // ---- LayerNorm 1 + ReLU ----
        s = a0 + a1;
        #pragma unroll
        for (int o = 16; o; o >>= 1) s += __shfl_xor_sync(0xffffffffu, s, o);
        mu = s * (1.f / 64.f);
        d0 = a0 - mu; d1 = a1 - mu;
        q = d0 * d0 + d1 * d1;
        #pragma unroll
        for (int o = 16; o; o >>= 1) q += __shfl_xor_sync(0xffffffffu, q, o);
        inv = rsqrtf(q * (1.f / 64.f) + 1e-5f);
        v0 = fmaxf(fmaf(d0 * inv, w1a, b1a), 0.f);
        v1 = fmaxf(fmaf(d1 * inv, w1b, b1b), 0.f);

        float* orow = out + (size_t)row * CH;
        orow[lane]      = v0;
        orow[lane + 32] = v1;
        cs0 += v0;
        cs1 += v1;
        __syncwarp();
    }

    // GraphNorm column-sum partials: register -> shared -> 64 global atomics.
    atomicAdd(&bsum[lane], cs0);
    atomicAdd(&bsum[lane + 32], cs1);
    __syncthreads();
    if (tid < CH) atomicAdd(&g_colsum[tid], bsum[tid]);
}

// ---------------------------------------------------------------------------
// K4: variance of (h2 - alpha*mean) per column. Thread's column fixed
// (tid % 64, stride multiple of 64).
// ---------------------------------------------------------------------------
__global__ void k_var(const float* __restrict__ gn_alpha,
                      const float* __restrict__ h2, int N) {
    const int c = threadIdx.x & 63;
    const float am = gn_alpha[c] * (g_colsum[c] / (float)N);
    const long long total = (long long)N * CH;
    float acc = 0.f;
    for (long long i = (long long)blockIdx.x * blockDim.x + threadIdx.x; i < total;
         i += (long long)gridDim.x * blockDim.x) {
        float d = h2[i] - am;
        acc = fmaf(d, d, acc);
    }
    __shared__ float sred[256];
    sred[threadIdx.x] = acc;
    __syncthreads();
    if (threadIdx.x < CH)
        atomicAdd(&g_varsum[c], sred[threadIdx.x] + sred[threadIdx.x + 64] +
                                sred[threadIdx.x + 128] + sred[threadIdx.x + 192]);
}

// ---------------------------------------------------------------------------
// K5: final GraphNorm, in-place on d_out.
// ---------------------------------------------------------------------------
__global__ void k_final(const float* __restrict__ gn_w, const float* __restrict__ gn_b,
                        const float* __restrict__ gn_alpha, float* __restrict__ out,
                        int N) {
    const int c = threadIdx.x & 63;
    const float am = gn_alpha[c] * (g_colsum[c] / (float)N);
    const float inv = rsqrtf(g_varsum[c] / (float)N + 1e-5f);
    const float w = gn_w[c] * inv;
    const float b = gn_b[c];
    const long long total = (long long)N * CH;
    for (long long i = (long long)blockIdx.x * blockDim.x + threadIdx.x; i < total;
         i += (long long)gridDim.x * blockDim.x) {
        out[i] = fmaf(out[i] - am, w, b);
    }
}

// ---------------------------------------------------------------------------
extern "C" void kernel_launch(void* const* d_in, const int* in_sizes, int n_in,
                              void* d_out, int out_size) {
    const float* x    = (const float*)d_in[0];
    const void*  ei   = d_in[1];
    const float* W0   = (const float*)d_in[2];
    const float* ln0w = (const float*)d_in[3];
    const float* ln0b = (const float*)d_in[4];
    const float* W1   = (const float*)d_in[5];
    const float* ln1w = (const float*)d_in[6];
    const float* ln1b = (const float*)d_in[7];
    const float* gnw  = (const float*)d_in[8];
    const float* gnb  = (const float*)d_in[9];
    const float* gna  = (const float*)d_in[10];

    const int N = in_sizes[0] / CH;
    const int E = in_sizes[1] / 2;
    float* out = (float*)d_out;

    const int n4 = N * CH / 4;
    k_init<<<(n4 + 255) / 256, 256>>>((const float4*)x, (const int*)ei, n4, E);

    const int total = E * 16;
    k_scatter<<<(total + 255) / 256, 256>>>(ei, (const float4*)x, E);

    k_mlp<<<888, 256>>>(W0, ln0w, ln0b, W1, ln1w, ln1b, out, N);

    k_var<<<2048, 256>>>(gna, out, N);
    k_final<<<2048, 256>>>(gnw, gnb, gna, out, N);
}

// round 3
// speedup vs baseline: 2.3094x; 2.3094x over previous
#include <cuda_runtime.h>

#define CH 64
#define MAXN 65536
#define MAXE 1100000

// Scratch (no allocs allowed).
__device__ int   g_deg[MAXN];
__device__ int   g_off[MAXN];
__device__ int   g_cursor[MAXN];
__device__ int   g_csr[MAXE];
__device__ int   g_blk[64];
__device__ int   g_blkoff[64];
__device__ float g_colsum[CH];
__device__ float g_sumsq[CH];
__device__ int   g_idx64;

// ---------------------------------------------------------------------------
// K1: zero degree counters + reduction buffers, detect index dtype.
// ---------------------------------------------------------------------------
__global__ void k_init(const int* __restrict__ ei32, int N, int E) {
    for (int i = blockIdx.x * blockDim.x + threadIdx.x; i < N;
         i += gridDim.x * blockDim.x)
        g_deg[i] = 0;
    if (blockIdx.x == 0) {
        if (threadIdx.x < CH) {
            g_colsum[threadIdx.x] = 0.f;
            g_sumsq[threadIdx.x]  = 0.f;
        }
        if (threadIdx.x == 0) {
            // int64 edge_index => high 32-bit word of every entry is 0.
            int allz = 1;
            int cnt = (E < 64) ? E : 64;
            for (int t = 0; t < cnt; t++) allz &= (ei32[2 * t + 1] == 0);
            g_idx64 = allz;
        }
    }
}

// ---------------------------------------------------------------------------
// K2: histogram of destination degrees.
// ---------------------------------------------------------------------------
__global__ void k_hist(const void* __restrict__ ei, int E) {
    const int idx64 = g_idx64;
    const long long* e64 = (const long long*)ei;
    const int*       e32 = (const int*)ei;
    for (int i = blockIdx.x * blockDim.x + threadIdx.x; i < E;
         i += gridDim.x * blockDim.x) {
        int dst = idx64 ? (int)e64[E + i] : e32[E + i];
        atomicAdd(&g_deg[dst], 1);
    }
}

// ---------------------------------------------------------------------------
// K3a/b/c: two-level exclusive scan of g_deg -> g_off (N <= 64 * 1024).
// ---------------------------------------------------------------------------
__global__ void k_scanA(int N) {
    __shared__ int s[1024];
    int tid = threadIdx.x;
    int i = blockIdx.x * 1024 + tid;
    int v = (i < N) ? g_deg[i] : 0;
    s[tid] = v;
    __syncthreads();
    for (int o = 1; o < 1024; o <<= 1) {
        int t = (tid >= o) ? s[tid - o] : 0;
        __syncthreads();
        s[tid] += t;
        __syncthreads();
    }
    if (i < N) g_off[i] = s[tid] - v;              // exclusive within tile
    if (tid == 1023) g_blk[blockIdx.x] = s[1023];  // tile total
}

__global__ void k_scanB(int NT) {
    __shared__ int s[64];
    int t = threadIdx.x;
    int v = (t < NT) ? g_blk[t] : 0;
    s[t] = v;
    __syncthreads();
    for (int o = 1; o < 64; o <<= 1) {
        int u = (t >= o) ? s[t - o] : 0;
        __syncthreads();
        s[t] += u;
        __syncthreads();
    }
    if (t < NT) g_blkoff[t] = s[t] - v;            // exclusive tile offsets
}

__global__ void k_scanC(int N) {
    int i = blockIdx.x * blockDim.x + threadIdx.x;
    if (i < N) {
        int o = g_off[i] + g_blkoff[i >> 10];
        g_off[i] = o;
        g_cursor[i] = o;
    }
}

// ---------------------------------------------------------------------------
// K4: fill CSR adjacency (dst -> list of src).
// ---------------------------------------------------------------------------
__global__ void k_fill(const void* __restrict__ ei, int E) {
    const int idx64 = g_idx64;
    const long long* e64 = (const long long*)ei;
    const int*       e32 = (const int*)ei;
    for (int i = blockIdx.x * blockDim.x + threadIdx.x; i < E;
         i += gridDim.x * blockDim.x) {
        int src, dst;
        if (idx64) { src = (int)e64[i]; dst = (int)e64[E + i]; }
        else       { src = e32[i];      dst = e32[E + i]; }
        int p = atomicAdd(&g_cursor[dst], 1);
        g_csr[p] = src;
    }
}

// ---------------------------------------------------------------------------
// K5: fused gather + MLP + GraphNorm partial sums. Warp handles 4 rows.
// For each row: h = x[row] + sum_{nb} x[nb]; then 2x (GEMM64 -> LN -> ReLU);
// h2 written to out; column sum & sumsq accumulated for GraphNorm.
// Weight smem padded to 68 floats/row: float4 reads stay conflict-free.
// ---------------------------------------------------------------------------
__global__ void k_mlp(const float* __restrict__ x,
                      const float* __restrict__ W0, const float* __restrict__ ln0w,
                      const float* __restrict__ ln0b, const float* __restrict__ W1,
                      const float* __restrict__ ln1w, const float* __restrict__ ln1b,
                      float* __restrict__ out, int N) {
    __shared__ __align__(16) float sW0[CH][68];
    __shared__ __align__(16) float sW1[CH][68];
    __shared__ __align__(16) float hbuf[8][4][CH];
    __shared__ float bsum[CH];
    __shared__ float bss[CH];

    const int tid  = threadIdx.x;
    const int lane = tid & 31;
    const int warp = tid >> 5;

    for (int i = tid; i < CH * CH; i += blockDim.x) {
        sW0[i >> 6][i & 63] = W0[i];
        sW1[i >> 6][i & 63] = W1[i];
    }
    if (tid < CH) { bsum[tid] = 0.f; bss[tid] = 0.f; }
    // zero h staging so tail rows never feed garbage into shuffles
    #pragma unroll
    for (int r = 0; r < 4; r++) {
        hbuf[warp][r][lane] = 0.f;
        hbuf[warp][r][lane + 32] = 0.f;
    }

    const float w0a = ln0w[lane], w0b = ln0w[lane + 32];
    const float b0a = ln0b[lane], b0b = ln0b[lane + 32];
    const float w1a = ln1w[lane], w1b = ln1w[lane + 32];
    const float b1a = ln1b[lane], b1b = ln1b[lane + 32];
    __syncthreads();

    const float4* wa0 = reinterpret_cast<const float4*>(&sW0[lane][0]);
    const float4* wb0 = reinterpret_cast<const float4*>(&sW0[lane + 32][0]);
    const float4* wa1 = reinterpret_cast<const float4*>(&sW1[lane][0]);
    const float4* wb1 = reinterpret_cast<const float4*>(&sW1[lane + 32][0]);
    const float2* x2  = reinterpret_cast<const float2*>(x);

    float cs0 = 0.f, cs1 = 0.f, ss0 = 0.f, ss1 = 0.f;

    const int gwarp   = blockIdx.x * 8 + warp;
    const int nwarps  = gridDim.x * 8;

    for (int base = gwarp * 4; base < N; base += nwarps * 4) {
        // ---- gather 4 rows: h = x[row] + sum of neighbor x rows ----
        #pragma unroll
        for (int r = 0; r < 4; r++) {
            int row = base + r;
            if (row < N) {
                int off = g_off[row];
                int deg = g_deg[row];
                float2 acc = x2[row * 32 + lane];
                for (int j = 0; j < deg; j++) {
                    int s = g_csr[off + j];          // broadcast load
                    float2 v = x2[s * 32 + lane];
                    acc.x += v.x; acc.y += v.y;
                }
                reinterpret_cast<float2*>(&hbuf[warp][r][0])[lane] = acc;
            }
        }
        __syncwarp();

        // ---- layer 0 GEMM (4 rows share W reads) ----
        float a0[4], a1[4];
        #pragma unroll
        for (int r = 0; r < 4; r++) { a0[r] = 0.f; a1[r] = 0.f; }
        #pragma unroll
        for (int kk = 0; kk < 16; kk++) {
            float4 wa = wa0[kk];
            float4 wb = wb0[kk];
            #pragma unroll
            for (int r = 0; r < 4; r++) {
                float4 hv = reinterpret_cast<const float4*>(&hbuf[warp][r][0])[kk];
                a0[r] = fmaf(hv.x, wa.x, a0[r]); a0[r] = fmaf(hv.y, wa.y, a0[r]);
                a0[r] = fmaf(hv.z, wa.z, a0[r]); a0[r] = fmaf(hv.w, wa.w, a0[r]);
                a1[r] = fmaf(hv.x, wb.x, a1[r]); a1[r] = fmaf(hv.y, wb.y, a1[r]);
                a1[r] = fmaf(hv.z, wb.z, a1[r]); a1[r] = fmaf(hv.w, wb.w, a1[r]);
            }
        }
        __syncwarp();

        // ---- LayerNorm 0 + ReLU, restage ----
        #pragma unroll
        for (int r = 0; r < 4; r++) {
            float s = a0[r] + a1[r];
            #pragma unroll
            for (int o = 16; o; o >>= 1) s += __shfl_xor_sync(0xffffffffu, s, o);
            float mu = s * (1.f / 64.f);
            float d0 = a0[r] - mu, d1 = a1[r] - mu;
            float q = d0 * d0 + d1 * d1;
            #pragma unroll
            for (int o = 16; o; o >>= 1) q += __shfl_xor_sync(0xffffffffu, q, o);
            float inv = rsqrtf(q * (1.f / 64.f) + 1e-5f);
            hbuf[warp][r][lane]      = fmaxf(fmaf(d0 * inv, w0a, b0a), 0.f);
            hbuf[warp][r][lane + 32] = fmaxf(fmaf(d1 * inv, w0b, b0b), 0.f);
        }
        __syncwarp();

        // ---- layer 1 GEMM ----
        #pragma unroll
        for (int r = 0; r < 4; r++) { a0[r] = 0.f; a1[r] = 0.f; }
        #pragma unroll
        for (int kk = 0; kk < 16; kk++) {
            float4 wa = wa1[kk];
            float4 wb = wb1[kk];
            #pragma unroll
            for (int r = 0; r < 4; r++) {
                float4 hv = reinterpret_cast<const float4*>(&hbuf[warp][r][0])[kk];
                a0[r] = fmaf(hv.x, wa.x, a0[r]); a0[r] = fmaf(hv.y, wa.y, a0[r]);
                a0[r] = fmaf(hv.z, wa.z, a0[r]); a0[r] = fmaf(hv.w, wa.w, a0[r]);
                a1[r] = fmaf(hv.x, wb.x, a1[r]); a1[r] = fmaf(hv.y, wb.y, a1[r]);
                a1[r] = fmaf(hv.z, wb.z, a1[r]); a1[r] = fmaf(hv.w, wb.w, a1[r]);
            }
        }

        // ---- LayerNorm 1 + ReLU + store + GraphNorm partials ----
        #pragma unroll
        for (int r = 0; r < 4; r++) {
            int row = base + r;
            float s = a0[r] + a1[r];
            #pragma unroll
            for (int o = 16; o; o >>= 1) s += __shfl_xor_sync(0xffffffffu, s, o);
            float mu = s * (1.f / 64.f);
            float d0 = a0[r] - mu, d1 = a1[r] - mu;
            float q = d0 * d0 + d1 * d1;
            #pragma unroll
            for (int o = 16; o; o >>= 1) q += __shfl_xor_sync(0xffffffffu, q, o);
            float inv = rsqrtf(q * (1.f / 64.f) + 1e-5f);
            float v0 = fmaxf(fmaf(d0 * inv, w1a, b1a), 0.f);
            float v1 = fmaxf(fmaf(d1 * inv, w1b, b1b), 0.f);
            if (row < N) {
                float* orow = out + (size_t)row * CH;
                orow[lane]      = v0;
                orow[lane + 32] = v1;
                cs0 += v0; cs1 += v1;
                ss0 = fmaf(v0, v0, ss0);
                ss1 = fmaf(v1, v1, ss1);
            }
        }
        __syncwarp();
    }

    // column sum / sumsq partials: register -> shared -> 128 global atomics.
    atomicAdd(&bsum[lane], cs0);
    atomicAdd(&bsum[lane + 32], cs1);
    atomicAdd(&bss[lane], ss0);
    atomicAdd(&bss[lane + 32], ss1);
    __syncthreads();
    if (tid < CH) {
        atomicAdd(&g_colsum[tid], bsum[tid]);
        atomicAdd(&g_sumsq[tid],  bss[tid]);
    }
}

// ---------------------------------------------------------------------------
// K6: final GraphNorm, in-place, float4. var = E[h^2] - 2*am*mu + am^2.
// blockDim=256 => grid stride multiple of 16 => per-thread channels fixed.
// ---------------------------------------------------------------------------
__global__ void k_final(const float* __restrict__ gnw, const float* __restrict__ gnb,
                        const float* __restrict__ gna, float* __restrict__ out,
                        int N) {
    const float invN = 1.f / (float)N;
    const int t = blockIdx.x * blockDim.x + threadIdx.x;
    const int c0 = (t & 15) * 4;
    float am[4], w[4], b[4];
    #pragma unroll
    for (int j = 0; j < 4; j++) {
        int c = c0 + j;
        float mu  = g_colsum[c] * invN;
        float a   = gna[c] * mu;
        float ex2 = g_sumsq[c] * invN;
        float var = ex2 - 2.f * a * mu + a * a;
        am[j] = a;
        w[j]  = gnw[c] * rsqrtf(var + 1e-5f);
        b[j]  = gnb[c];
    }
    float4* o4 = reinterpret_cast<float4*>(out);
    const int total = N * 16;
    for (int i = t; i < total; i += gridDim.x * blockDim.x) {
        float4 h = o4[i];
        h.x = fmaf(h.x - am[0], w[0], b[0]);
        h.y = fmaf(h.y - am[1], w[1], b[1]);
        h.z = fmaf(h.z - am[2], w[2], b[2]);
        h.w = fmaf(h.w - am[3], w[3], b[3]);
        o4[i] = h;
    }
}

// ---------------------------------------------------------------------------
extern "C" void kernel_launch(void* const* d_in, const int* in_sizes, int n_in,
                              void* d_out, int out_size) {
    const float* x    = (const float*)d_in[0];
    const void*  ei   = d_in[1];
    const float* W0   = (const float*)d_in[2];
    const float* ln0w = (const float*)d_in[3];
    const float* ln0b = (const float*)d_in[4];
    const float* W1   = (const float*)d_in[5];
    const float* ln1w = (const float*)d_in[6];
    const float* ln1b = (const float*)d_in[7];
    const float* gnw  = (const float*)d_in[8];
    const float* gnb  = (const float*)d_in[9];
    const float* gna  = (const float*)d_in[10];

    const int N = in_sizes[0] / CH;
    const int E = in_sizes[1] / 2;
    float* out = (float*)d_out;

    const int NT = (N + 1023) / 1024;

    k_init<<<64, 256>>>((const int*)ei, N, E);
    k_hist<<<(E + 255) / 256, 256>>>(ei, E);
    k_scanA<<<NT, 1024>>>(N);
    k_scanB<<<1, 64>>>(NT);
    k_scanC<<<(N + 255) / 256, 256>>>(N);
    k_fill<<<(E + 255) / 256, 256>>>(ei, E);

    const int ngroups = (N + 3) / 4;                 // warps needed
    const int mlp_blocks = (ngroups + 7) / 8;        // 8 warps per block
    k_mlp<<<mlp_blocks, 256>>>(x, W0, ln0w, ln0b, W1, ln1w, ln1b, out, N);

    k_final<<<2048, 256>>>(gnw, gnb, gna, out, N);
}

// round 4
// speedup vs baseline: 2.3660x; 1.0245x over previous
#include <cuda_runtime.h>

#define CH 64
#define MAXN 65536
#define MAXE 1100000

// Scratch (no allocs allowed).
__device__ int   g_deg[MAXN];
__device__ int   g_off[MAXN];
__device__ int   g_cursor[MAXN];
__device__ int   g_csr[MAXE];
__device__ int   g_total;
__device__ float g_colsum[CH];
__device__ float g_sumsq[CH];
__device__ int   g_idx64;

#define FFMA2(acc, a, b) \
    asm("fma.rn.f32x2 %0, %1, %2, %0;" : "+l"(acc) : "l"(a), "l"(b))
#define PACK2(out, lo, hi) \
    asm("mov.b64 %0, {%1, %2};" : "=l"(out) : "f"(lo), "f"(hi))
#define UNPACK2(lo, hi, in) \
    asm("mov.b64 {%0, %1}, %2;" : "=f"(lo), "=f"(hi) : "l"(in))

// ---------------------------------------------------------------------------
// K1: zero counters + reduction buffers, detect index dtype.
// ---------------------------------------------------------------------------
__global__ void k_init(const int* __restrict__ ei32, int N, int E) {
    for (int i = blockIdx.x * blockDim.x + threadIdx.x; i < N;
         i += gridDim.x * blockDim.x)
        g_deg[i] = 0;
    if (blockIdx.x == 0) {
        if (threadIdx.x < CH) {
            g_colsum[threadIdx.x] = 0.f;
            g_sumsq[threadIdx.x]  = 0.f;
        }
        if (threadIdx.x == 0) {
            g_total = 0;
            // int64 edge_index => high 32-bit word of every entry is 0.
            int allz = 1;
            int cnt = (E < 64) ? E : 64;
            for (int t = 0; t < cnt; t++) allz &= (ei32[2 * t + 1] == 0);
            g_idx64 = allz;
        }
    }
}

// ---------------------------------------------------------------------------
// K2: histogram of destination degrees.
// ---------------------------------------------------------------------------
__global__ void k_hist(const void* __restrict__ ei, int E) {
    const int idx64 = g_idx64;
    const long long* e64 = (const long long*)ei;
    const int*       e32 = (const int*)ei;
    for (int i = blockIdx.x * blockDim.x + threadIdx.x; i < E;
         i += gridDim.x * blockDim.x) {
        int dst = idx64 ? (int)e64[E + i] : e32[E + i];
        atomicAdd(&g_deg[dst], 1);
    }
}

// ---------------------------------------------------------------------------
// K3: single-kernel offsets: block-local smem scan + atomic block base.
// CSR slot placement is run-order dependent (rel_err-tolerated), content isn't.
// ---------------------------------------------------------------------------
__global__ void k_off(int N) {
    __shared__ int s[1024];
    __shared__ int sbase;
    int tid = threadIdx.x;
    int i = blockIdx.x * 1024 + tid;
    int v = (i < N) ? g_deg[i] : 0;
    s[tid] = v;
    __syncthreads();
    for (int o = 1; o < 1024; o <<= 1) {
        int t = (tid >= o) ? s[tid - o] : 0;
        __syncthreads();
        s[tid] += t;
        __syncthreads();
    }
    if (tid == 1023) sbase = atomicAdd(&g_total, s[1023]);
    __syncthreads();
    if (i < N) {
        int o = sbase + s[tid] - v;
        g_off[i] = o;
        g_cursor[i] = o;
    }
}

// ---------------------------------------------------------------------------
// K4: fill CSR adjacency (dst -> list of src).
// ---------------------------------------------------------------------------
__global__ void k_fill(const void* __restrict__ ei, int E) {
    const int idx64 = g_idx64;
    const long long* e64 = (const long long*)ei;
    const int*       e32 = (const int*)ei;
    for (int i = blockIdx.x * blockDim.x + threadIdx.x; i < E;
         i += gridDim.x * blockDim.x) {
        int src, dst;
        if (idx64) { src = (int)e64[i]; dst = (int)e64[E + i]; }
        else       { src = e32[i];      dst = e32[E + i]; }
        int p = atomicAdd(&g_cursor[dst], 1);
        g_csr[p] = src;
    }
}

// ---------------------------------------------------------------------------
// Packed-pair 64x64 GEMM: rows (2p,2p+1) live in f32x2 lanes; weight scalar
// duplicated via mov.b64 (ALU pipe) so FFMA-pipe instr count halves.
// ---------------------------------------------------------------------------
__device__ __forceinline__ void gemm64_packed(
    const float4* __restrict__ wa, const float4* __restrict__ wb,
    const float* __restrict__ hrow0, const float* __restrict__ hrow1,
    const float* __restrict__ hrow2, const float* __restrict__ hrow3,
    float* a0, float* a1) {
    unsigned long long pa[2][2] = {{0ull, 0ull}, {0ull, 0ull}};
    const float4* h[4] = {
        reinterpret_cast<const float4*>(hrow0),
        reinterpret_cast<const float4*>(hrow1),
        reinterpret_cast<const float4*>(hrow2),
        reinterpret_cast<const float4*>(hrow3)};
    #pragma unroll
    for (int kk = 0; kk < 16; kk++) {
        float4 va = wa[kk];
        float4 vb = wb[kk];
        unsigned long long wax, way, waz, waw, wbx, wby, wbz, wbw;
        PACK2(wax, va.x, va.x); PACK2(way, va.y, va.y);
        PACK2(waz, va.z, va.z); PACK2(waw, va.w, va.w);
        PACK2(wbx, vb.x, vb.x); PACK2(wby, vb.y, vb.y);
        PACK2(wbz, vb.z, vb.z); PACK2(wbw, vb.w, vb.w);
        #pragma unroll
        for (int p = 0; p < 2; p++) {
            float4 h0 = h[2 * p][kk];
            float4 h1 = h[2 * p + 1][kk];
            unsigned long long hx, hy, hz, hw;
            PACK2(hx, h0.x, h1.x); PACK2(hy, h0.y, h1.y);
            PACK2(hz, h0.z, h1.z); PACK2(hw, h0.w, h1.w);
            FFMA2(pa[p][0], hx, wax); FFMA2(pa[p][0], hy, way);
            FFMA2(pa[p][0], hz, waz); FFMA2(pa[p][0], hw, waw);
            FFMA2(pa[p][1], hx, wbx); FFMA2(pa[p][1], hy, wby);
            FFMA2(pa[p][1], hz, wbz); FFMA2(pa[p][1], hw, wbw);
        }
    }
    #pragma unroll
    for (int p = 0; p < 2; p++) {
        UNPACK2(a0[2 * p], a0[2 * p + 1], pa[p][0]);
        UNPACK2(a1[2 * p], a1[2 * p + 1], pa[p][1]);
    }
}

// ---------------------------------------------------------------------------
// K5: fused gather + MLP + GraphNorm partial sums. Warp handles 4 rows.
// ---------------------------------------------------------------------------
__global__ void k_mlp(const float* __restrict__ x,
                      const float* __restrict__ W0, const float* __restrict__ ln0w,
                      const float* __restrict__ ln0b, const float* __restrict__ W1,
                      const float* __restrict__ ln1w, const float* __restrict__ ln1b,
                      float* __restrict__ out, int N) {
    __shared__ __align__(16) float sW0[CH][68];
    __shared__ __align__(16) float sW1[CH][68];
    __shared__ __align__(16) float hbuf[8][4][CH];
    __shared__ float bsum[CH];
    __shared__ float bss[CH];

    const int tid  = threadIdx.x;
    const int lane = tid & 31;
    const int warp = tid >> 5;

    for (int i = tid; i < CH * CH; i += blockDim.x) {
        sW0[i >> 6][i & 63] = W0[i];
        sW1[i >> 6][i & 63] = W1[i];
    }
    if (tid < CH) { bsum[tid] = 0.f; bss[tid] = 0.f; }
    #pragma unroll
    for (int r = 0; r < 4; r++) {
        hbuf[warp][r][lane] = 0.f;
        hbuf[warp][r][lane + 32] = 0.f;
    }

    const float w0a = ln0w[lane], w0b = ln0w[lane + 32];
    const float b0a = ln0b[lane], b0b = ln0b[lane + 32];
    const float w1a = ln1w[lane], w1b = ln1w[lane + 32];
    const float b1a = ln1b[lane], b1b = ln1b[lane + 32];
    __syncthreads();

    const float4* wa0 = reinterpret_cast<const float4*>(&sW0[lane][0]);
    const float4* wb0 = reinterpret_cast<const float4*>(&sW0[lane + 32][0]);
    const float4* wa1 = reinterpret_cast<const float4*>(&sW1[lane][0]);
    const float4* wb1 = reinterpret_cast<const float4*>(&sW1[lane + 32][0]);
    const float2* x2  = reinterpret_cast<const float2*>(x);

    float cs0 = 0.f, cs1 = 0.f, ss0 = 0.f, ss1 = 0.f;

    const int gwarp  = blockIdx.x * 8 + warp;
    const int nwarps = gridDim.x * 8;

    for (int base = gwarp * 4; base < N; base += nwarps * 4) {
        // ---- gather: h = x[row] + sum of neighbor rows (csr prefetch) ----
        #pragma unroll
        for (int r = 0; r < 4; r++) {
            int row = base + r;
            if (row < N) {
                int off = g_off[row];
                int deg = g_deg[row];
                float2 acc = x2[row * 32 + lane];
                if (deg > 0) {
                    int s = g_csr[off];
                    int j = 0;
                    for (; j + 1 < deg; j++) {
                        int sn = g_csr[off + j + 1];   // prefetch next index
                        float2 v = x2[s * 32 + lane];
                        acc.x += v.x; acc.y += v.y;
                        s = sn;
                    }
                    float2 v = x2[s * 32 + lane];
                    acc.x += v.x; acc.y += v.y;
                }
                reinterpret_cast<float2*>(&hbuf[warp][r][0])[lane] = acc;
            }
        }
        __syncwarp();

        // ---- layer 0 GEMM ----
        float a0[4], a1[4];
        gemm64_packed(wa0, wb0, &hbuf[warp][0][0], &hbuf[warp][1][0],
                      &hbuf[warp][2][0], &hbuf[warp][3][0], a0, a1);
        __syncwarp();

        // ---- LayerNorm 0 + ReLU, restage ----
        #pragma unroll
        for (int r = 0; r < 4; r++) {
            float s = a0[r] + a1[r];
            #pragma unroll
            for (int o = 16; o; o >>= 1) s += __shfl_xor_sync(0xffffffffu, s, o);
            float mu = s * (1.f / 64.f);
            float d0 = a0[r] - mu, d1 = a1[r] - mu;
            float q = d0 * d0 + d1 * d1;
            #pragma unroll
            for (int o = 16; o; o >>= 1) q += __shfl_xor_sync(0xffffffffu, q, o);
            float inv = rsqrtf(q * (1.f / 64.f) + 1e-5f);
            hbuf[warp][r][lane]      = fmaxf(fmaf(d0 * inv, w0a, b0a), 0.f);
            hbuf[warp][r][lane + 32] = fmaxf(fmaf(d1 * inv, w0b, b0b), 0.f);
        }
        __syncwarp();

        // ---- layer 1 GEMM ----
        gemm64_packed(wa1, wb1, &hbuf[warp][0][0], &hbuf[warp][1][0],
                      &hbuf[warp][2][0], &hbuf[warp][3][0], a0, a1);

        // ---- LayerNorm 1 + ReLU + store + GraphNorm partials ----
        #pragma unroll
        for (int r = 0; r < 4; r++) {
            int row = base + r;
            float s = a0[r] + a1[r];
            #pragma unroll
            for (int o = 16; o; o >>= 1) s += __shfl_xor_sync(0xffffffffu, s, o);
            float mu = s * (1.f / 64.f);
            float d0 = a0[r] - mu, d1 = a1[r] - mu;
            float q = d0 * d0 + d1 * d1;
            #pragma unroll
            for (int o = 16; o; o >>= 1) q += __shfl_xor_sync(0xffffffffu, q, o);
            float inv = rsqrtf(q * (1.f / 64.f) + 1e-5f);
            float v0 = fmaxf(fmaf(d0 * inv, w1a, b1a), 0.f);
            float v1 = fmaxf(fmaf(d1 * inv, w1b, b1b), 0.f);
            if (row < N) {
                float* orow = out + (size_t)row * CH;
                orow[lane]      = v0;
                orow[lane + 32] = v1;
                cs0 += v0; cs1 += v1;
                ss0 = fmaf(v0, v0, ss0);
                ss1 = fmaf(v1, v1, ss1);
            }
        }
        __syncwarp();
    }

    // column sum / sumsq partials: register -> shared -> 128 global atomics.
    atomicAdd(&bsum[lane], cs0);
    atomicAdd(&bsum[lane + 32], cs1);
    atomicAdd(&bss[lane], ss0);
    atomicAdd(&bss[lane + 32], ss1);
    __syncthreads();
    if (tid < CH) {
        atomicAdd(&g_colsum[tid], bsum[tid]);
        atomicAdd(&g_sumsq[tid],  bss[tid]);
    }
}

// ---------------------------------------------------------------------------
// K6: final GraphNorm, in-place, float4. var = E[h^2] - 2*am*mu + am^2.
// ---------------------------------------------------------------------------
__global__ void k_final(const float* __restrict__ gnw, const float* __restrict__ gnb,
                        const float* __restrict__ gna, float* __restrict__ out,
                        int N) {
    const float invN = 1.f / (float)N;
    const int t = blockIdx.x * blockDim.x + threadIdx.x;
    const int c0 = (t & 15) * 4;
    float am[4], w[4], b[4];
    #pragma unroll
    for (int j = 0; j < 4; j++) {
        int c = c0 + j;
        float mu  = g_colsum[c] * invN;
        float a   = gna[c] * mu;
        float ex2 = g_sumsq[c] * invN;
        float var = ex2 - 2.f * a * mu + a * a;
        am[j] = a;
        w[j]  = gnw[c] * rsqrtf(var + 1e-5f);
        b[j]  = gnb[c];
    }
    float4* o4 = reinterpret_cast<float4*>(out);
    const int total = N * 16;
    for (int i = t; i < total; i += gridDim.x * blockDim.x) {
        float4 h = o4[i];
        h.x = fmaf(h.x - am[0], w[0], b[0]);
        h.y = fmaf(h.y - am[1], w[1], b[1]);
        h.z = fmaf(h.z - am[2], w[2], b[2]);
        h.w = fmaf(h.w - am[3], w[3], b[3]);
        o4[i] = h;
    }
}

// ---------------------------------------------------------------------------
extern "C" void kernel_launch(void* const* d_in, const int* in_sizes, int n_in,
                              void* d_out, int out_size) {
    const float* x    = (const float*)d_in[0];
    const void*  ei   = d_in[1];
    const float* W0   = (const float*)d_in[2];
    const float* ln0w = (const float*)d_in[3];
    const float* ln0b = (const float*)d_in[4];
    const float* W1   = (const float*)d_in[5];
    const float* ln1w = (const float*)d_in[6];
    const float* ln1b = (const float*)d_in[7];
    const float* gnw  = (const float*)d_in[8];
    const float* gnb  = (const float*)d_in[9];
    const float* gna  = (const float*)d_in[10];

    const int N = in_sizes[0] / CH;
    const int E = in_sizes[1] / 2;
    float* out = (float*)d_out;

    k_init<<<64, 256>>>((const int*)ei, N, E);
    k_hist<<<(E + 255) / 256, 256>>>(ei, E);
    k_off<<<(N + 1023) / 1024, 1024>>>(N);
    k_fill<<<(E + 255) / 256, 256>>>(ei, E);

    const int ngroups = (N + 3) / 4;                 // warps needed
    const int mlp_blocks = (ngroups + 7) / 8;        // 8 warps per block
    k_mlp<<<mlp_blocks, 256>>>(x, W0, ln0w, ln0b, W1, ln1w, ln1b, out, N);

    k_final<<<2048, 256>>>(gnw, gnb, gna, out, N);
}